// round 5
// baseline (speedup 1.0000x reference)
#include <cuda_runtime.h>
#include <math.h>

// Problem constants (fixed by setup_inputs)
#define Bdim 4
#define Sdim 1024
#define Ddim 256
#define Hn   6
#define Hd   64
#define HF   384          // Hn*Hd
#define En   3
#define SENT_END 988      // S - sect - doc
#define SECT_END 1020     // S - doc
#define MAXDEG 256
#define BS  (Bdim*Sdim)   // 4096
#define BSD (BS*Ddim)     // 1048576

// ----------------------------- device scratch -----------------------------
__device__ __align__(128) int   g_nbr[BS*MAXDEG];      // CSR neighbor lists (sorted by j)
__device__ __align__(128) int   g_cnt[BS*3];           // cumulative counts: <988, <1020, total
__device__ __align__(128) float g_mask[En*BS];         // routing mask per expert
__device__ __align__(128) float g_W1t[4*Ddim*HF];      // W1 transposed to [D, H*Hd] (main + 3 dep)
__device__ __align__(128) float g_h [BS*HF];
__device__ __align__(128) float g_h1[BS*HF];
__device__ __align__(128) float g_h2[BS*Ddim];
__device__ __align__(128) float g_es[Bdim*Hn*Sdim];
__device__ __align__(128) float g_ed[Bdim*Hn*Sdim];
__device__ __align__(128) float g_s2[BS];
__device__ __align__(128) float g_d2[BS];
__device__ __align__(128) float g_main[BSD];
__device__ __align__(128) float g_dep[BSD];
__device__ __align__(128) float g_blend[BSD];
__device__ __align__(128) float g_meanh[Bdim*HF];
__device__ __align__(128) float g_meanh2[Bdim*Ddim];
__device__ __align__(128) float g_part[1024];

// packed fp32x2 FMA (Blackwell FFMA2 — only reachable via PTX)
__device__ __forceinline__ unsigned long long ffma2(
    unsigned long long a, unsigned long long b, unsigned long long c) {
    unsigned long long d;
    asm("fma.rn.f32x2 %0, %1, %2, %3;" : "=l"(d) : "l"(a), "l"(b), "l"(c));
    return d;
}
__device__ __forceinline__ float lo32(unsigned long long v) {
    return __uint_as_float((unsigned)(v & 0xffffffffull));
}
__device__ __forceinline__ float hi32(unsigned long long v) {
    return __uint_as_float((unsigned)(v >> 32));
}

// ----------------------------- kernels -----------------------------

__global__ void k_zero_dep() {
    g_dep[(size_t)blockIdx.x*256 + threadIdx.x] = 0.f;
}

// one warp per row: compact adjacency row into CSR (preserves ascending j order)
__global__ void k_build_csr(const float* __restrict__ adj) {
    int warp = (blockIdx.x*blockDim.x + threadIdx.x) >> 5;
    int lane = threadIdx.x & 31;
    if (warp >= BS) return;
    const float* row = adj + (size_t)warp * Sdim;
    int cnt = 0, c0 = 0, c1 = 0;
    for (int c = 0; c < Sdim; c += 32) {
        int j = c + lane;
        float v = row[j];
        unsigned m = __ballot_sync(0xffffffffu, v > 0.f);
        if (v > 0.f) {
            int pos = cnt + __popc(m & ((1u << lane) - 1u));
            if (pos < MAXDEG) g_nbr[warp*MAXDEG + pos] = j;
        }
        unsigned msent = __ballot_sync(0xffffffffu, j < SENT_END);
        unsigned msect = __ballot_sync(0xffffffffu, j < SECT_END);
        cnt += __popc(m);
        c0  += __popc(m & msent);
        c1  += __popc(m & msect);
    }
    if (lane == 0) {
        g_cnt[warp*3+0] = c0; g_cnt[warp*3+1] = c1; g_cnt[warp*3+2] = cnt;
    }
}

// one warp per node: router logits; top-2 of 3 == exclude argmin (ties -> larger idx)
__global__ void k_router(const float* __restrict__ x, const float* __restrict__ rw) {
    int warp = (blockIdx.x*blockDim.x + threadIdx.x) >> 5;
    int lane = threadIdx.x & 31;
    if (warp >= BS) return;
    const float* xp = x + (size_t)warp * Ddim;
    float l0 = 0.f, l1 = 0.f, l2 = 0.f;
    for (int d = lane; d < Ddim; d += 32) {
        float v = xp[d];
        l0 += v * rw[d*3+0];
        l1 += v * rw[d*3+1];
        l2 += v * rw[d*3+2];
    }
    for (int o = 16; o; o >>= 1) {
        l0 += __shfl_xor_sync(0xffffffffu, l0, o);
        l1 += __shfl_xor_sync(0xffffffffu, l1, o);
        l2 += __shfl_xor_sync(0xffffffffu, l2, o);
    }
    if (lane == 0) {
        int excl = 0; float mn = l0;
        if (l1 <= mn) { mn = l1; excl = 1; }
        if (l2 <= mn) { mn = l2; excl = 2; }
        g_mask[0*BS + warp] = (excl == 0) ? 0.f : 1.f;
        g_mask[1*BS + warp] = (excl == 1) ? 0.f : 1.f;
        g_mask[2*BS + warp] = (excl == 2) ? 0.f : 1.f;
    }
}

// transpose W1 [H,D,Hd] -> [D, H*Hd], for main (slot 0) and 3 deputies
__global__ void k_transW1(const float* __restrict__ mW1, const float* __restrict__ dW1) {
    int i = blockIdx.x*blockDim.x + threadIdx.x;
    if (i >= 4*Ddim*HF) return;
    int e = i / (Ddim*HF);
    int r = i - e*(Ddim*HF);
    int f = r / HF;
    int ho = r - f*HF;
    int hh = ho >> 6, o = ho & 63;
    const float* src = (e == 0) ? mW1 : (dW1 + (size_t)(e-1)*Hn*Ddim*Hd);
    g_W1t[i] = src[(hh*Ddim + f)*Hd + o];
}

// ---------------------------------------------------------------------------
// FFMA2 SGEMM: C[M,N] = A[M,K] @ B[K,N], optional per-row output mask.
// Tile 128x64, 256 threads, micro-tile 8M x 4N per thread, accumulators packed
// along M into f32x2 pairs. B tile stored DUPLICATED in smem so a 16B LDS
// yields two (b,b) broadcast pairs. Double-buffered smem, register prefetch.
// Requires M%128==0, N%64==0, K%16==0.
// ---------------------------------------------------------------------------
#define TKk 16
__global__ void __launch_bounds__(256) k_sgemm(
    const float* __restrict__ A, const float* __restrict__ B, float* __restrict__ C,
    int M, int N, int K, const float* __restrict__ rowmask)
{
    __shared__ __align__(16) float As[2][TKk][136];   // padded: row stride 544B (16B multiple)
    __shared__ __align__(16) float Bs[2][TKk][128];   // duplicated pairs: [2n]=[2n+1]=b[n]
    int tid = threadIdx.x;
    int tx = tid & 15;   // N micro: 4 cols
    int ty = tid >> 4;   // M micro: 8 rows (4 f32x2 pairs)
    const float* Ab = A + (size_t)blockIdx.y*128*K;
    const float* Bb = B + blockIdx.x*64;

    // global-load indexing
    int ar = tid >> 1;          // A row 0..127
    int ac = (tid & 1) * 8;     // A col offset 0/8 (two float4)
    int br = tid >> 4;          // B k-row 0..15
    int bc = (tid & 15) * 4;    // B col 0..60

    unsigned long long acc[4][4];
    #pragma unroll
    for (int i = 0; i < 4; i++)
        #pragma unroll
        for (int j = 0; j < 4; j++) acc[i][j] = 0ull;

    // ---- stage 0 load ----
    {
        float4 a0 = *(const float4*)(Ab + (size_t)ar*K + ac);
        float4 a1 = *(const float4*)(Ab + (size_t)ar*K + ac + 4);
        float4 b0 = *(const float4*)(Bb + (size_t)br*N + bc);
        #pragma unroll
        for (int i = 0; i < 4; i++) {
            As[0][ac+i][ar]   = ((float*)&a0)[i];
            As[0][ac+4+i][ar] = ((float*)&a1)[i];
        }
        float4 d0 = make_float4(b0.x, b0.x, b0.y, b0.y);
        float4 d1 = make_float4(b0.z, b0.z, b0.w, b0.w);
        *(float4*)&Bs[0][br][bc*2]     = d0;
        *(float4*)&Bs[0][br][bc*2 + 4] = d1;
    }
    __syncthreads();

    int nstage = K / TKk;
    for (int s = 0; s < nstage; s++) {
        int cur = s & 1, nxt = cur ^ 1;
        float4 pa0, pa1, pb;
        bool has_next = (s + 1 < nstage);
        if (has_next) {
            int kn = (s + 1) * TKk;
            pa0 = *(const float4*)(Ab + (size_t)ar*K + kn + ac);
            pa1 = *(const float4*)(Ab + (size_t)ar*K + kn + ac + 4);
            pb  = *(const float4*)(Bb + (size_t)(kn + br)*N + bc);
        }
        #pragma unroll
        for (int k = 0; k < TKk; k++) {
            const ulonglong2* ap2 = (const ulonglong2*)&As[cur][k][ty*8];
            const ulonglong2* bp2 = (const ulonglong2*)&Bs[cur][k][tx*8];
            ulonglong2 a01 = ap2[0];
            ulonglong2 a23 = ap2[1];
            ulonglong2 b01 = bp2[0];
            ulonglong2 b23 = bp2[1];
            unsigned long long ap[4] = {a01.x, a01.y, a23.x, a23.y};
            unsigned long long bd[4] = {b01.x, b01.y, b23.x, b23.y};
            #pragma unroll
            for (int i = 0; i < 4; i++)
                #pragma unroll
                for (int j = 0; j < 4; j++)
                    acc[i][j] = ffma2(ap[i], bd[j], acc[i][j]);
        }
        if (has_next) {
            #pragma unroll
            for (int i = 0; i < 4; i++) {
                As[nxt][ac+i][ar]   = ((float*)&pa0)[i];
                As[nxt][ac+4+i][ar] = ((float*)&pa1)[i];
            }
            float4 d0 = make_float4(pb.x, pb.x, pb.y, pb.y);
            float4 d1 = make_float4(pb.z, pb.z, pb.w, pb.w);
            *(float4*)&Bs[nxt][br][bc*2]     = d0;
            *(float4*)&Bs[nxt][br][bc*2 + 4] = d1;
        }
        __syncthreads();
    }

    // ---- epilogue ----
    #pragma unroll
    for (int mp = 0; mp < 4; mp++) {
        int row0 = blockIdx.y*128 + ty*8 + 2*mp;
        float mv0 = rowmask ? rowmask[row0]   : 1.f;
        float mv1 = rowmask ? rowmask[row0+1] : 1.f;
        float4 vlo = make_float4(lo32(acc[mp][0]), lo32(acc[mp][1]),
                                 lo32(acc[mp][2]), lo32(acc[mp][3]));
        float4 vhi = make_float4(hi32(acc[mp][0]), hi32(acc[mp][1]),
                                 hi32(acc[mp][2]), hi32(acc[mp][3]));
        vlo.x *= mv0; vlo.y *= mv0; vlo.z *= mv0; vlo.w *= mv0;
        vhi.x *= mv1; vhi.y *= mv1; vhi.z *= mv1; vhi.w *= mv1;
        *(float4*)(C + (size_t)row0*N     + blockIdx.x*64 + tx*4) = vlo;
        *(float4*)(C + (size_t)(row0+1)*N + blockIdx.x*64 + tx*4) = vhi;
    }
}

// per-(b,h,s) attention source/dest projections for layer 1
__global__ void k_esed(const float* __restrict__ a1s, const float* __restrict__ a1d) {
    int idx = blockIdx.x*blockDim.x + threadIdx.x;
    if (idx >= Bdim*Hn*Sdim) return;
    int s  = idx & (Sdim-1);
    int bh = idx >> 10;
    int hh = bh % Hn;
    int b  = bh / Hn;
    const float* hp = g_h + ((size_t)(b*Sdim + s))*HF + hh*Hd;
    const float* as = a1s + hh*Hd;
    const float* ad = a1d + hh*Hd;
    float x = 0.f, y = 0.f;
    #pragma unroll 8
    for (int o = 0; o < Hd; o++) { float v = hp[o]; x += v*as[o]; y += v*ad[o]; }
    g_es[idx] = x; g_ed[idx] = y;
}

// layer-1 sparse attention + ELU.  expert: -1 main (full CSR), 0/1/2 deputy (segment)
__global__ void __launch_bounds__(384) k_att1(int expert) {
    int row = blockIdx.x;
    int b = row >> 10, s = row & 1023;
    __shared__ float sc[Hn][MAXDEG];
    __shared__ int   snbr[MAXDEG];
    __shared__ float sden[Hn];
    const int* c = g_cnt + row*3;
    int lo = 0, hi;
    if      (expert < 0)  hi = c[2];
    else if (expert == 0) hi = c[0];
    else if (expert == 1) { lo = c[0]; hi = c[1]; }
    else                  { lo = c[1]; hi = c[2]; }
    int deg = hi - lo;
    int tid = threadIdx.x;
    if (deg == 0) {  // all scores -1e9 -> uniform attention over all S -> column mean
        for (int o = tid; o < HF; o += 384) {
            float v = g_meanh[b*HF + o];
            g_h1[(size_t)row*HF + o] = (v > 0.f) ? v : expm1f(v);
        }
        return;
    }
    for (int j = tid; j < deg; j += 384) snbr[j] = g_nbr[row*MAXDEG + lo + j];
    __syncthreads();
    for (int idx = tid; idx < Hn*deg; idx += 384) {
        int hh = idx / deg;
        int j  = idx - hh*deg;
        float v = g_es[(b*Hn+hh)*Sdim + s] + g_ed[(b*Hn+hh)*Sdim + snbr[j]];
        sc[hh][j] = (v > 0.f) ? v : 0.2f*v;
    }
    __syncthreads();
    int warp = tid >> 5, lane = tid & 31;
    if (warp < Hn) {
        float m = -1e30f;
        for (int j = lane; j < deg; j += 32) m = fmaxf(m, sc[warp][j]);
        for (int o = 16; o; o >>= 1) m = fmaxf(m, __shfl_xor_sync(0xffffffffu, m, o));
        float su = 0.f;
        for (int j = lane; j < deg; j += 32) { float e = expf(sc[warp][j] - m); sc[warp][j] = e; su += e; }
        for (int o = 16; o; o >>= 1) su += __shfl_xor_sync(0xffffffffu, su, o);
        if (lane == 0) sden[warp] = su;
    }
    __syncthreads();
    int hh = tid >> 6, o = tid & 63;
    const float* hb = g_h + (size_t)(b*Sdim)*HF + hh*Hd + o;
    float acc0 = 0.f, acc1 = 0.f;
    int j = 0;
    for (; j + 1 < deg; j += 2) {
        acc0 += sc[hh][j]   * hb[(size_t)snbr[j]*HF];
        acc1 += sc[hh][j+1] * hb[(size_t)snbr[j+1]*HF];
    }
    if (j < deg) acc0 += sc[hh][j] * hb[(size_t)snbr[j]*HF];
    float v = (acc0 + acc1) / sden[hh];
    g_h1[(size_t)row*HF + hh*Hd + o] = (v > 0.f) ? v : expm1f(v);
}

__global__ void k_s2d2(const float* __restrict__ a2s, const float* __restrict__ a2d) {
    int row = blockIdx.x*blockDim.x + threadIdx.x;
    if (row >= BS) return;
    const float* p = g_h2 + (size_t)row*Ddim;
    float x = 0.f, y = 0.f;
    #pragma unroll 8
    for (int d = 0; d < Ddim; d++) { float v = p[d]; x += v*a2s[d]; y += v*a2d[d]; }
    g_s2[row] = x; g_d2[row] = y;
}

// layer-2 sparse attention; main writes g_main, deputies accumulate masked rows into g_dep
__global__ void __launch_bounds__(256) k_att2(int expert) {
    int row = blockIdx.x;
    if (expert >= 0 && g_mask[expert*BS + row] == 0.f) return;  // output masked anyway
    int b = row >> 10;
    __shared__ float sc[MAXDEG];
    __shared__ int   snbr[MAXDEG];
    __shared__ float sden;
    const int* c = g_cnt + row*3;
    int lo = 0, hi;
    if      (expert < 0)  hi = c[2];
    else if (expert == 0) hi = c[0];
    else if (expert == 1) { lo = c[0]; hi = c[1]; }
    else                  { lo = c[1]; hi = c[2]; }
    int deg = hi - lo;
    int tid = threadIdx.x;
    if (deg == 0) {
        for (int o = tid; o < Ddim; o += 256) {
            float v = g_meanh2[b*Ddim + o];
            if (expert < 0) g_main[(size_t)row*Ddim + o] = v;
            else            g_dep [(size_t)row*Ddim + o] += v;
        }
        return;
    }
    for (int j = tid; j < deg; j += 256) snbr[j] = g_nbr[row*MAXDEG + lo + j];
    __syncthreads();
    float srcsc = g_s2[row];
    for (int j = tid; j < deg; j += 256) {
        float v = srcsc + g_d2[b*Sdim + snbr[j]];
        sc[j] = (v > 0.f) ? v : 0.2f*v;
    }
    __syncthreads();
    if (tid < 32) {
        float m = -1e30f;
        for (int j = tid; j < deg; j += 32) m = fmaxf(m, sc[j]);
        for (int o = 16; o; o >>= 1) m = fmaxf(m, __shfl_xor_sync(0xffffffffu, m, o));
        float su = 0.f;
        for (int j = tid; j < deg; j += 32) { float e = expf(sc[j] - m); sc[j] = e; su += e; }
        for (int o = 16; o; o >>= 1) su += __shfl_xor_sync(0xffffffffu, su, o);
        if (tid == 0) sden = su;
    }
    __syncthreads();
    const float* hb = g_h2 + (size_t)(b*Sdim)*Ddim + tid;
    float acc0 = 0.f, acc1 = 0.f;
    int j = 0;
    for (; j + 1 < deg; j += 2) {
        acc0 += sc[j]   * hb[(size_t)snbr[j]*Ddim];
        acc1 += sc[j+1] * hb[(size_t)snbr[j+1]*Ddim];
    }
    if (j < deg) acc0 += sc[j] * hb[(size_t)snbr[j]*Ddim];
    float v = (acc0 + acc1) / sden;
    if (expert < 0) g_main[(size_t)row*Ddim + tid] = v;
    else            g_dep [(size_t)row*Ddim + tid] += v;
}

// column means per batch (for zero-degree uniform-attention rows)
__global__ void k_colmean(const float* __restrict__ X, float* __restrict__ out, int cols) {
    int idx = blockIdx.x*blockDim.x + threadIdx.x;
    if (idx >= Bdim*cols) return;
    int b = idx / cols, cc = idx - b*cols;
    const float* p = X + (size_t)b*Sdim*cols + cc;
    float a0 = 0.f, a1 = 0.f, a2 = 0.f, a3 = 0.f;
    for (int r = 0; r < Sdim; r += 4) {
        a0 += p[(size_t)r*cols];
        a1 += p[(size_t)(r+1)*cols];
        a2 += p[(size_t)(r+2)*cols];
        a3 += p[(size_t)(r+3)*cols];
    }
    out[idx] = (a0 + a1 + a2 + a3) * (1.f/(float)Sdim);
}

// blend + final output + deterministic partial sums of blend weights
__global__ void __launch_bounds__(256) k_final(const float* __restrict__ bbias, float* __restrict__ out) {
    __shared__ float red[256];
    int t = threadIdx.x;
    int base = blockIdx.x*1024;
    float s = 0.f;
    #pragma unroll
    for (int l = 0; l < 4; l++) {
        int i = base + l*256 + t;
        int d = i & (Ddim-1);
        float w = 1.f / (1.f + expf(-(g_blend[i] + bbias[d])));
        out[i] = w*g_main[i] + (1.f - w)*g_dep[i];
        s += w;
    }
    red[t] = s; __syncthreads();
    for (int o = 128; o; o >>= 1) { if (t < o) red[t] += red[t+o]; __syncthreads(); }
    if (t == 0) g_part[blockIdx.x] = red[0];
}

__global__ void k_scalar(float* __restrict__ out) {
    __shared__ float red[256];
    int t = threadIdx.x;
    float s = 0.f;
    for (int i = t; i < 1024; i += 256) s += g_part[i];
    red[t] = s; __syncthreads();
    for (int o = 128; o; o >>= 1) { if (t < o) red[t] += red[t+o]; __syncthreads(); }
    if (t == 0) {
        float mc = red[0] / (float)BSD;
        out[BSD]     = fabsf(mc - 0.6f) * 0.01f;
        out[BSD + 1] = mc;
    }
}

// ----------------------------- host launcher -----------------------------
extern "C" void kernel_launch(void* const* d_in, const int* in_sizes, int n_in,
                              void* d_out, int out_size) {
    const float* feature = (const float*)d_in[0];
    const float* adj     = (const float*)d_in[1];
    const float* mW1     = (const float*)d_in[2];
    const float* ma1s    = (const float*)d_in[3];
    const float* ma1d    = (const float*)d_in[4];
    const float* mW2     = (const float*)d_in[5];
    const float* ma2s    = (const float*)d_in[6];
    const float* ma2d    = (const float*)d_in[7];
    const float* dW1     = (const float*)d_in[8];
    const float* da1s    = (const float*)d_in[9];
    const float* da1d    = (const float*)d_in[10];
    const float* dW2     = (const float*)d_in[11];
    const float* da2s    = (const float*)d_in[12];
    const float* da2d    = (const float*)d_in[13];
    const float* rW      = (const float*)d_in[14];
    const float* bW      = (const float*)d_in[15];
    const float* bbias   = (const float*)d_in[16];
    float* out = (float*)d_out;

    static float *p_h = nullptr, *p_h1, *p_h2, *p_W1t, *p_mask, *p_blend, *p_meanh, *p_meanh2;
    if (!p_h) {
        cudaGetSymbolAddress((void**)&p_h,      g_h);
        cudaGetSymbolAddress((void**)&p_h1,     g_h1);
        cudaGetSymbolAddress((void**)&p_h2,     g_h2);
        cudaGetSymbolAddress((void**)&p_W1t,    g_W1t);
        cudaGetSymbolAddress((void**)&p_mask,   g_mask);
        cudaGetSymbolAddress((void**)&p_blend,  g_blend);
        cudaGetSymbolAddress((void**)&p_meanh,  g_meanh);
        cudaGetSymbolAddress((void**)&p_meanh2, g_meanh2);
    }

    k_zero_dep<<<4096, 256>>>();
    k_router  <<<512, 256>>>(feature, rW);
    k_build_csr<<<512, 256>>>(adj);
    k_transW1 <<<1536, 256>>>(mW1, dW1);

    dim3 gemm1(HF/64, BS/128);    // N=384
    dim3 gemm2(Ddim/64, BS/128);  // N=256

    // ---- main expert ----
    k_sgemm<<<gemm1, 256>>>(feature, p_W1t, p_h, BS, HF, Ddim, nullptr);
    k_esed <<<96, 256>>>(ma1s, ma1d);
    k_att1 <<<4096, 384>>>(-1);
    k_sgemm<<<gemm2, 256>>>(p_h1, mW2, p_h2, BS, Ddim, HF, nullptr);
    k_s2d2 <<<16, 256>>>(ma2s, ma2d);
    k_att2 <<<4096, 256>>>(-1);

    // ---- deputy experts ----
    for (int e = 0; e < En; e++) {
        k_sgemm<<<gemm1, 256>>>(feature, p_W1t + (size_t)(1+e)*Ddim*HF, p_h, BS, HF, Ddim, p_mask + e*BS);
        k_esed <<<96, 256>>>(da1s + e*Hn*Hd, da1d + e*Hn*Hd);
        k_colmean<<<6, 256>>>(p_h, p_meanh, HF);
        k_att1 <<<4096, 384>>>(e);
        k_sgemm<<<gemm2, 256>>>(p_h1, dW2 + (size_t)e*HF*Ddim, p_h2, BS, Ddim, HF, nullptr);
        k_s2d2 <<<16, 256>>>(da2s + e*Ddim, da2d + e*Ddim);
        k_colmean<<<4, 256>>>(p_h2, p_meanh2, Ddim);
        k_att2 <<<4096, 256>>>(e);
    }

    // ---- blend + final ----
    k_sgemm<<<gemm2, 256>>>(feature, bW, p_blend, BS, Ddim, Ddim, nullptr);
    k_final<<<1024, 256>>>(bbias, out);
    if (out_size >= BSD + 2) k_scalar<<<1, 256>>>(out);
}

// round 7
// speedup vs baseline: 1.9256x; 1.9256x over previous
#include <cuda_runtime.h>
#include <math.h>

// Problem constants (fixed by setup_inputs)
#define Bdim 4
#define Sdim 1024
#define Ddim 256
#define Hn   6
#define Hd   64
#define HF   384          // Hn*Hd
#define En   3
#define SENT_END 988      // S - sect - doc
#define SECT_END 1020     // S - doc
#define MAXDEG 256
#define BS  (Bdim*Sdim)   // 4096
#define BSD (BS*Ddim)     // 1048576
#define NBIG 1792         // 4*HF + Ddim  (4 experts layer-1 + blend)
#define LDH  1792         // g_hall row stride
#define LDH1 1536         // g_h1all row stride (4*HF)
#define LDH2 1024         // g_h2all row stride (4*Ddim)
#define ESN  (Bdim*Hn*Sdim)  // 24576 per expert

// ----------------------------- device scratch -----------------------------
__device__ __align__(128) int   g_nbr[BS*MAXDEG];      // CSR neighbor lists (ascending j)
__device__ __align__(128) int   g_cnt[BS*3];           // cumulative counts: <988, <1020, total
__device__ __align__(128) float g_mask[En*BS];         // routing mask per deputy expert
__device__ __align__(128) float g_Bpack[Ddim*NBIG];    // packed B: [W1t m|d0|d1|d2 | bW]
__device__ __align__(128) float g_hall [BS*LDH];       // layer-1 out (4 experts) + blend logits
__device__ __align__(128) float g_h1all[BS*LDH1];      // att1+ELU out, 4 experts
__device__ __align__(128) float g_h2all[BS*LDH2];      // layer-2 out, 4 experts
__device__ __align__(128) float g_es[4*ESN];
__device__ __align__(128) float g_ed[4*ESN];
__device__ __align__(128) float g_s2[4*BS];
__device__ __align__(128) float g_d2[4*BS];
__device__ __align__(128) float g_main[BSD];
__device__ __align__(128) float g_dep3[En*BSD];        // per-deputy att2 outputs
__device__ __align__(128) float g_meanh [Bdim*LDH1];   // column means of g_hall (per b)
__device__ __align__(128) float g_meanh2[Bdim*LDH2];   // column means of g_h2all (per b)
__device__ __align__(128) float g_part[1024];

// ----------------------------- kernels -----------------------------

// one warp per row: compact adjacency row into CSR (preserves ascending j order)
__global__ void k_build_csr(const float* __restrict__ adj) {
    int warp = (blockIdx.x*blockDim.x + threadIdx.x) >> 5;
    int lane = threadIdx.x & 31;
    if (warp >= BS) return;
    const float* row = adj + (size_t)warp * Sdim;
    int cnt = 0, c0 = 0, c1 = 0;
    for (int c = 0; c < Sdim; c += 32) {
        int j = c + lane;
        float v = row[j];
        unsigned m = __ballot_sync(0xffffffffu, v > 0.f);
        if (v > 0.f) {
            int pos = cnt + __popc(m & ((1u << lane) - 1u));
            if (pos < MAXDEG) g_nbr[warp*MAXDEG + pos] = j;
        }
        unsigned msent = __ballot_sync(0xffffffffu, j < SENT_END);
        unsigned msect = __ballot_sync(0xffffffffu, j < SECT_END);
        cnt += __popc(m);
        c0  += __popc(m & msent);
        c1  += __popc(m & msect);
    }
    if (lane == 0) {
        g_cnt[warp*3+0] = c0; g_cnt[warp*3+1] = c1; g_cnt[warp*3+2] = cnt;
    }
}

// one warp per node: router logits; top-2 of 3 == exclude argmin (ties -> larger idx)
__global__ void k_router(const float* __restrict__ x, const float* __restrict__ rw) {
    int warp = (blockIdx.x*blockDim.x + threadIdx.x) >> 5;
    int lane = threadIdx.x & 31;
    if (warp >= BS) return;
    const float* xp = x + (size_t)warp * Ddim;
    float l0 = 0.f, l1 = 0.f, l2 = 0.f;
    for (int d = lane; d < Ddim; d += 32) {
        float v = xp[d];
        l0 += v * rw[d*3+0];
        l1 += v * rw[d*3+1];
        l2 += v * rw[d*3+2];
    }
    for (int o = 16; o; o >>= 1) {
        l0 += __shfl_xor_sync(0xffffffffu, l0, o);
        l1 += __shfl_xor_sync(0xffffffffu, l1, o);
        l2 += __shfl_xor_sync(0xffffffffu, l2, o);
    }
    if (lane == 0) {
        int excl = 0; float mn = l0;
        if (l1 <= mn) { mn = l1; excl = 1; }
        if (l2 <= mn) { mn = l2; excl = 2; }
        g_mask[0*BS + warp] = (excl == 0) ? 0.f : 1.f;
        g_mask[1*BS + warp] = (excl == 1) ? 0.f : 1.f;
        g_mask[2*BS + warp] = (excl == 2) ? 0.f : 1.f;
    }
}

// build packed B [D=256 rows][NBIG=1792 cols]:
// cols [e*384 + hh*64 + o] = W1[e][hh][f][o] transposed; cols [1536+d] = bW[f][d]
__global__ void k_pack(const float* __restrict__ mW1, const float* __restrict__ dW1,
                       const float* __restrict__ bW) {
    int i = blockIdx.x*blockDim.x + threadIdx.x;
    if (i >= Ddim*NBIG) return;
    int f   = i / NBIG;
    int col = i - f*NBIG;
    float v;
    if (col < 4*HF) {
        int e  = col / HF;
        int ho = col - e*HF;
        int hh = ho >> 6, o = ho & 63;
        const float* src = (e == 0) ? mW1 : (dW1 + (size_t)(e-1)*Hn*Ddim*Hd);
        v = src[(hh*Ddim + f)*Hd + o];
    } else {
        v = bW[f*Ddim + (col - 4*HF)];
    }
    g_Bpack[i] = v;
}

// ---------------------------------------------------------------------------
// Fused big SGEMM: g_hall[4096,1792] = feature[4096,256] @ g_Bpack[256,1792]
// Tile 128x64, 256 threads, 8Mx4N micro-tile. Per-column-block rowmask for
// deputy expert segments (zeroing unrouted input rows' h).
// ---------------------------------------------------------------------------
__global__ void __launch_bounds__(256) k_gemm_big(const float* __restrict__ A) {
    __shared__ __align__(16) float As[16][128];
    __shared__ __align__(16) float Bs[16][64];
    int tid = threadIdx.x;
    int tx = tid & 15;   // N micro (x4)
    int ty = tid >> 4;   // M micro (x8)
    int bx = blockIdx.x; // N tile (0..27)
    int by = blockIdx.y; // M tile (0..31)
    // blocks 0-5: main (no mask), 6-11: dep0, 12-17: dep1, 18-23: dep2, 24-27: blend
    const float* rowmask = nullptr;
    int seg = bx / 6;
    if (bx < 24 && seg > 0) rowmask = g_mask + (size_t)(seg-1)*BS;

    const float* Ab = A + (size_t)by*128*Ddim;
    const float* Bb = g_Bpack + bx*64;
    float acc[8][4];
    #pragma unroll
    for (int i = 0; i < 8; i++)
        #pragma unroll
        for (int j = 0; j < 4; j++) acc[i][j] = 0.f;

    for (int k0 = 0; k0 < Ddim; k0 += 16) {
        #pragma unroll
        for (int l = 0; l < 2; l++) {
            int q  = tid + l*256;
            int r  = q >> 2;
            int c4 = q & 3;
            float4 v = *(const float4*)(Ab + (size_t)r*Ddim + k0 + c4*4);
            As[c4*4+0][r] = v.x; As[c4*4+1][r] = v.y;
            As[c4*4+2][r] = v.z; As[c4*4+3][r] = v.w;
        }
        {
            int r  = tid >> 4;
            int c4 = tid & 15;
            float4 v = *(const float4*)(Bb + (size_t)(k0 + r)*NBIG + c4*4);
            *(float4*)&Bs[r][c4*4] = v;
        }
        __syncthreads();
        #pragma unroll
        for (int k = 0; k < 16; k++) {
            float4 a0 = *(const float4*)&As[k][ty*8];
            float4 a1 = *(const float4*)&As[k][ty*8+4];
            float4 b0 = *(const float4*)&Bs[k][tx*4];
            float a[8] = {a0.x,a0.y,a0.z,a0.w,a1.x,a1.y,a1.z,a1.w};
            float bb[4] = {b0.x,b0.y,b0.z,b0.w};
            #pragma unroll
            for (int i = 0; i < 8; i++)
                #pragma unroll
                for (int j = 0; j < 4; j++) acc[i][j] += a[i]*bb[j];
        }
        __syncthreads();
    }
    #pragma unroll
    for (int i = 0; i < 8; i++) {
        int row = by*128 + ty*8 + i;
        float mv = rowmask ? rowmask[row] : 1.f;
        float* cp = g_hall + (size_t)row*LDH + bx*64 + tx*4;
        cp[0] = acc[i][0]*mv; cp[1] = acc[i][1]*mv;
        cp[2] = acc[i][2]*mv; cp[3] = acc[i][3]*mv;
    }
}

// ---------------------------------------------------------------------------
// Batched layer-2 SGEMM over blockIdx.z = expert (0=main, 1..3 deputies):
// g_h2all[:, z*256:(z+1)*256] = g_h1all[:, z*384:(z+1)*384] @ W2_z[384,256]
// ---------------------------------------------------------------------------
__global__ void __launch_bounds__(256) k_gemm2(const float* __restrict__ mW2,
                                               const float* __restrict__ dW2) {
    __shared__ __align__(16) float As[16][128];
    __shared__ __align__(16) float Bs[16][64];
    int tid = threadIdx.x;
    int tx = tid & 15;
    int ty = tid >> 4;
    int bx = blockIdx.x;  // 0..3 (N=256)
    int by = blockIdx.y;  // 0..31
    int z  = blockIdx.z;  // expert
    const float* A  = g_h1all + (size_t)z*HF;                    // lda = LDH1
    const float* Bp = (z == 0) ? mW2 : (dW2 + (size_t)(z-1)*HF*Ddim);  // ldb = 256
    const float* Ab = A + (size_t)by*128*LDH1;
    const float* Bb = Bp + bx*64;

    float acc[8][4];
    #pragma unroll
    for (int i = 0; i < 8; i++)
        #pragma unroll
        for (int j = 0; j < 4; j++) acc[i][j] = 0.f;

    for (int k0 = 0; k0 < HF; k0 += 16) {
        #pragma unroll
        for (int l = 0; l < 2; l++) {
            int q  = tid + l*256;
            int r  = q >> 2;
            int c4 = q & 3;
            float4 v = *(const float4*)(Ab + (size_t)r*LDH1 + k0 + c4*4);
            As[c4*4+0][r] = v.x; As[c4*4+1][r] = v.y;
            As[c4*4+2][r] = v.z; As[c4*4+3][r] = v.w;
        }
        {
            int r  = tid >> 4;
            int c4 = tid & 15;
            float4 v = *(const float4*)(Bb + (size_t)(k0 + r)*Ddim + c4*4);
            *(float4*)&Bs[r][c4*4] = v;
        }
        __syncthreads();
        #pragma unroll
        for (int k = 0; k < 16; k++) {
            float4 a0 = *(const float4*)&As[k][ty*8];
            float4 a1 = *(const float4*)&As[k][ty*8+4];
            float4 b0 = *(const float4*)&Bs[k][tx*4];
            float a[8] = {a0.x,a0.y,a0.z,a0.w,a1.x,a1.y,a1.z,a1.w};
            float bb[4] = {b0.x,b0.y,b0.z,b0.w};
            #pragma unroll
            for (int i = 0; i < 8; i++)
                #pragma unroll
                for (int j = 0; j < 4; j++) acc[i][j] += a[i]*bb[j];
        }
        __syncthreads();
    }
    #pragma unroll
    for (int i = 0; i < 8; i++) {
        int row = by*128 + ty*8 + i;
        float* cp = g_h2all + (size_t)row*LDH2 + z*Ddim + bx*64 + tx*4;
        cp[0] = acc[i][0]; cp[1] = acc[i][1];
        cp[2] = acc[i][2]; cp[3] = acc[i][3];
    }
}

// batched es/ed projections for all 4 experts
__global__ void k_esed4(const float* __restrict__ ma1s, const float* __restrict__ ma1d,
                        const float* __restrict__ da1s, const float* __restrict__ da1d) {
    int idx = blockIdx.x*blockDim.x + threadIdx.x;
    if (idx >= 4*ESN) return;
    int e = idx / ESN;
    int r = idx - e*ESN;
    int s  = r & (Sdim-1);
    int bh = r >> 10;
    int hh = bh % Hn;
    int b  = bh / Hn;
    const float* hp = g_hall + (size_t)(b*Sdim + s)*LDH + e*HF + hh*Hd;
    const float* as = ((e == 0) ? ma1s : da1s + (e-1)*Hn*Hd) + hh*Hd;
    const float* ad = ((e == 0) ? ma1d : da1d + (e-1)*Hn*Hd) + hh*Hd;
    float x = 0.f, y = 0.f;
    #pragma unroll 8
    for (int o = 0; o < Hd; o++) { float v = hp[o]; x += v*as[o]; y += v*ad[o]; }
    g_es[idx] = x; g_ed[idx] = y;
}

// generic per-batch column mean: out[b*cols + c] = mean_r X[(b*Sdim + r)*ldx + c]
__global__ void k_colmean(const float* __restrict__ X, int ldx, int cols, float* __restrict__ out) {
    int idx = blockIdx.x*blockDim.x + threadIdx.x;
    if (idx >= Bdim*cols) return;
    int b = idx / cols, cc = idx - b*cols;
    const float* p = X + (size_t)b*Sdim*ldx + cc;
    float a0 = 0.f, a1 = 0.f, a2 = 0.f, a3 = 0.f;
    for (int r = 0; r < Sdim; r += 4) {
        a0 += p[(size_t)r*ldx];
        a1 += p[(size_t)(r+1)*ldx];
        a2 += p[(size_t)(r+2)*ldx];
        a3 += p[(size_t)(r+3)*ldx];
    }
    out[idx] = (a0 + a1 + a2 + a3) * (1.f/(float)Sdim);
}

// layer-1 sparse attention + ELU, batched: blockIdx.y = 0 main, 1..3 deputy
__global__ void __launch_bounds__(384) k_att1(void) {
    int row = blockIdx.x;
    int ee  = blockIdx.y;
    int b = row >> 10, s = row & 1023;
    __shared__ float sc[Hn][MAXDEG];
    __shared__ int   snbr[MAXDEG];
    __shared__ float sden[Hn];
    const int* c = g_cnt + row*3;
    int lo = 0, hi;
    if      (ee == 0) hi = c[2];
    else if (ee == 1) hi = c[0];
    else if (ee == 2) { lo = c[0]; hi = c[1]; }
    else              { lo = c[1]; hi = c[2]; }
    int deg = hi - lo;
    int tid = threadIdx.x;
    if (deg == 0) {  // all scores -1e9 -> uniform attention over all S -> column mean
        for (int o = tid; o < HF; o += 384) {
            float v = g_meanh[b*LDH1 + ee*HF + o];
            g_h1all[(size_t)row*LDH1 + ee*HF + o] = (v > 0.f) ? v : expm1f(v);
        }
        return;
    }
    for (int j = tid; j < deg; j += 384) snbr[j] = g_nbr[row*MAXDEG + lo + j];
    __syncthreads();
    const float* esb = g_es + ee*ESN + b*Hn*Sdim;
    const float* edb = g_ed + ee*ESN + b*Hn*Sdim;
    for (int idx = tid; idx < Hn*deg; idx += 384) {
        int hh = idx / deg;
        int j  = idx - hh*deg;
        float v = esb[hh*Sdim + s] + edb[hh*Sdim + snbr[j]];
        sc[hh][j] = (v > 0.f) ? v : 0.2f*v;
    }
    __syncthreads();
    int warp = tid >> 5, lane = tid & 31;
    if (warp < Hn) {
        float m = -1e30f;
        for (int j = lane; j < deg; j += 32) m = fmaxf(m, sc[warp][j]);
        for (int o = 16; o; o >>= 1) m = fmaxf(m, __shfl_xor_sync(0xffffffffu, m, o));
        float su = 0.f;
        for (int j = lane; j < deg; j += 32) { float e = expf(sc[warp][j] - m); sc[warp][j] = e; su += e; }
        for (int o = 16; o; o >>= 1) su += __shfl_xor_sync(0xffffffffu, su, o);
        if (lane == 0) sden[warp] = su;
    }
    __syncthreads();
    int hh = tid >> 6, o = tid & 63;
    const float* hb = g_hall + (size_t)(b*Sdim)*LDH + ee*HF + hh*Hd + o;
    float acc0 = 0.f, acc1 = 0.f;
    int j = 0;
    for (; j + 1 < deg; j += 2) {
        acc0 += sc[hh][j]   * hb[(size_t)snbr[j]*LDH];
        acc1 += sc[hh][j+1] * hb[(size_t)snbr[j+1]*LDH];
    }
    if (j < deg) acc0 += sc[hh][j] * hb[(size_t)snbr[j]*LDH];
    float v = (acc0 + acc1) / sden[hh];
    g_h1all[(size_t)row*LDH1 + ee*HF + hh*Hd + o] = (v > 0.f) ? v : expm1f(v);
}

// batched layer-2 attention projections
__global__ void k_s2d24(const float* __restrict__ ma2s, const float* __restrict__ ma2d,
                        const float* __restrict__ da2s, const float* __restrict__ da2d) {
    int idx = blockIdx.x*blockDim.x + threadIdx.x;
    if (idx >= 4*BS) return;
    int e   = idx / BS;
    int row = idx - e*BS;
    const float* p  = g_h2all + (size_t)row*LDH2 + e*Ddim;
    const float* as = (e == 0) ? ma2s : da2s + (e-1)*Ddim;
    const float* ad = (e == 0) ? ma2d : da2d + (e-1)*Ddim;
    float x = 0.f, y = 0.f;
    #pragma unroll 8
    for (int d = 0; d < Ddim; d++) { float v = p[d]; x += v*as[d]; y += v*ad[d]; }
    g_s2[idx] = x; g_d2[idx] = y;
}

// layer-2 sparse attention, batched: y=0 main -> g_main; y=1..3 -> g_dep3[e]
__global__ void __launch_bounds__(256) k_att2(void) {
    int row = blockIdx.x;
    int ee  = blockIdx.y;
    if (ee > 0 && g_mask[(ee-1)*BS + row] == 0.f) return;  // output masked anyway
    int b = row >> 10;
    __shared__ float sc[MAXDEG];
    __shared__ int   snbr[MAXDEG];
    __shared__ float sden;
    const int* c = g_cnt + row*3;
    int lo = 0, hi;
    if      (ee == 0) hi = c[2];
    else if (ee == 1) hi = c[0];
    else if (ee == 2) { lo = c[0]; hi = c[1]; }
    else              { lo = c[1]; hi = c[2]; }
    int deg = hi - lo;
    int tid = threadIdx.x;
    float* outp = (ee == 0) ? (g_main + (size_t)row*Ddim)
                            : (g_dep3 + (size_t)(ee-1)*BSD + (size_t)row*Ddim);
    if (deg == 0) {
        for (int o = tid; o < Ddim; o += 256)
            outp[o] = g_meanh2[b*LDH2 + ee*Ddim + o];
        return;
    }
    for (int j = tid; j < deg; j += 256) snbr[j] = g_nbr[row*MAXDEG + lo + j];
    __syncthreads();
    float srcsc = g_s2[ee*BS + row];
    const float* d2b = g_d2 + ee*BS + b*Sdim;
    for (int j = tid; j < deg; j += 256) {
        float v = srcsc + d2b[snbr[j]];
        sc[j] = (v > 0.f) ? v : 0.2f*v;
    }
    __syncthreads();
    if (tid < 32) {
        float m = -1e30f;
        for (int j = tid; j < deg; j += 32) m = fmaxf(m, sc[j]);
        for (int o = 16; o; o >>= 1) m = fmaxf(m, __shfl_xor_sync(0xffffffffu, m, o));
        float su = 0.f;
        for (int j = tid; j < deg; j += 32) { float e = expf(sc[j] - m); sc[j] = e; su += e; }
        for (int o = 16; o; o >>= 1) su += __shfl_xor_sync(0xffffffffu, su, o);
        if (tid == 0) sden = su;
    }
    __syncthreads();
    const float* hb = g_h2all + (size_t)(b*Sdim)*LDH2 + ee*Ddim + tid;
    float acc0 = 0.f, acc1 = 0.f;
    int j = 0;
    for (; j + 1 < deg; j += 2) {
        acc0 += sc[j]   * hb[(size_t)snbr[j]*LDH2];
        acc1 += sc[j+1] * hb[(size_t)snbr[j+1]*LDH2];
    }
    if (j < deg) acc0 += sc[j] * hb[(size_t)snbr[j]*LDH2];
    outp[tid] = (acc0 + acc1) / sden;
}

// blend + final output + deterministic partial sums of blend weights
__global__ void __launch_bounds__(256) k_final(const float* __restrict__ bbias, float* __restrict__ out) {
    __shared__ float red[256];
    int t = threadIdx.x;
    int base = blockIdx.x*1024;
    float s = 0.f;
    #pragma unroll
    for (int l = 0; l < 4; l++) {
        int i   = base + l*256 + t;
        int row = i >> 8;
        int d   = i & (Ddim-1);
        float blendv = g_hall[(size_t)row*LDH + 4*HF + d];
        float w = 1.f / (1.f + expf(-(blendv + bbias[d])));
        float dep = g_mask[0*BS + row] * g_dep3[0*BSD + i]
                  + g_mask[1*BS + row] * g_dep3[1*BSD + i]
                  + g_mask[2*BS + row] * g_dep3[2*BSD + i];
        out[i] = w*g_main[i] + (1.f - w)*dep;
        s += w;
    }
    red[t] = s; __syncthreads();
    for (int o = 128; o; o >>= 1) { if (t < o) red[t] += red[t+o]; __syncthreads(); }
    if (t == 0) g_part[blockIdx.x] = red[0];
}

__global__ void k_scalar(float* __restrict__ out) {
    __shared__ float red[256];
    int t = threadIdx.x;
    float s = 0.f;
    for (int i = t; i < 1024; i += 256) s += g_part[i];
    red[t] = s; __syncthreads();
    for (int o = 128; o; o >>= 1) { if (t < o) red[t] += red[t+o]; __syncthreads(); }
    if (t == 0) {
        float mc = red[0] / (float)BSD;
        out[BSD]     = fabsf(mc - 0.6f) * 0.01f;
        out[BSD + 1] = mc;
    }
}

// ----------------------------- host launcher -----------------------------
extern "C" void kernel_launch(void* const* d_in, const int* in_sizes, int n_in,
                              void* d_out, int out_size) {
    const float* feature = (const float*)d_in[0];
    const float* adj     = (const float*)d_in[1];
    const float* mW1     = (const float*)d_in[2];
    const float* ma1s    = (const float*)d_in[3];
    const float* ma1d    = (const float*)d_in[4];
    const float* mW2     = (const float*)d_in[5];
    const float* ma2s    = (const float*)d_in[6];
    const float* ma2d    = (const float*)d_in[7];
    const float* dW1     = (const float*)d_in[8];
    const float* da1s    = (const float*)d_in[9];
    const float* da1d    = (const float*)d_in[10];
    const float* dW2     = (const float*)d_in[11];
    const float* da2s    = (const float*)d_in[12];
    const float* da2d    = (const float*)d_in[13];
    const float* rW      = (const float*)d_in[14];
    const float* bW      = (const float*)d_in[15];
    const float* bbias   = (const float*)d_in[16];
    float* out = (float*)d_out;

    static float *p_hall = nullptr, *p_h2all, *p_meanh, *p_meanh2;
    if (!p_hall) {
        cudaGetSymbolAddress((void**)&p_hall,   g_hall);
        cudaGetSymbolAddress((void**)&p_h2all,  g_h2all);
        cudaGetSymbolAddress((void**)&p_meanh,  g_meanh);
        cudaGetSymbolAddress((void**)&p_meanh2, g_meanh2);
    }

    k_router   <<<512, 256>>>(feature, rW);
    k_build_csr<<<512, 256>>>(adj);
    k_pack     <<<(Ddim*NBIG + 255)/256, 256>>>(mW1, dW1, bW);

    // fused layer-1 (4 experts) + blend GEMM: 896 CTAs
    k_gemm_big<<<dim3(NBIG/64, BS/128), 256>>>(feature);

    k_esed4  <<<(4*ESN + 255)/256, 256>>>(ma1s, ma1d, da1s, da1d);
    k_colmean<<<(Bdim*LDH1 + 255)/256, 256>>>(p_hall, LDH, LDH1, p_meanh);

    k_att1<<<dim3(BS, 4), 384>>>();

    // batched layer-2 GEMM over 4 experts: 512 CTAs
    k_gemm2<<<dim3(Ddim/64, BS/128, 4), 256>>>(mW2, dW2);

    k_s2d24  <<<(4*BS + 255)/256, 256>>>(ma2s, ma2d, da2s, da2d);
    k_colmean<<<(Bdim*LDH2 + 255)/256, 256>>>(p_h2all, LDH2, LDH2, p_meanh2);

    k_att2<<<dim3(BS, 4), 256>>>();

    k_final<<<1024, 256>>>(bbias, out);
    if (out_size >= BSD + 2) k_scalar<<<1, 256>>>(out);
}